// round 2
// baseline (speedup 1.0000x reference)
#include <cuda_runtime.h>
#include <math.h>

#define NN 50000
#define EE 800000
#define ETOT (EE + NN)
#define DIM 128
#define HH 4
#define CC 32
#define NEG_SLOPE 0.2f

// ---------------- device scratch (no allocations allowed) ----------------
__device__ int   g_count[NN];
__device__ int   g_rowptr[NN + 1];
__device__ int   g_cursor[NN];
__device__ int   g_colidx[ETOT];
__device__ float g_h[NN * DIM];      // activated layer input (layers 2,3)
__device__ float g_hw[NN * DIM];     // transformed features of current layer
__device__ float g_asrc[NN * HH];
__device__ float g_adst[NN * HH];

// ---------------- CSR build ----------------
__global__ void k_init_count() {
    int i = blockIdx.x * blockDim.x + threadIdx.x;
    if (i < NN) g_count[i] = 1;   // self loop pre-counted
}

__global__ void k_count(const int* __restrict__ ei) {
    int e = blockIdx.x * blockDim.x + threadIdx.x;
    if (e < EE) atomicAdd(&g_count[ei[EE + e]], 1);
}

// single-block sequential-chunk exclusive scan (N=50000)
__global__ void k_scan() {
    __shared__ int sdata[1024];
    __shared__ int carry;
    if (threadIdx.x == 0) carry = 0;
    __syncthreads();
    for (int base = 0; base < NN; base += 1024) {
        int i = base + threadIdx.x;
        int v = (i < NN) ? g_count[i] : 0;
        sdata[threadIdx.x] = v;
        __syncthreads();
        #pragma unroll
        for (int off = 1; off < 1024; off <<= 1) {
            int t = (threadIdx.x >= off) ? sdata[threadIdx.x - off] : 0;
            __syncthreads();
            sdata[threadIdx.x] += t;
            __syncthreads();
        }
        int excl = carry + sdata[threadIdx.x] - v;
        if (i < NN) { g_rowptr[i] = excl; g_cursor[i] = excl; }
        int tot = sdata[1023];
        __syncthreads();
        if (threadIdx.x == 0) carry += tot;
        __syncthreads();
    }
    if (threadIdx.x == 0) g_rowptr[NN] = carry;   // == ETOT
}

__global__ void k_fill(const int* __restrict__ ei) {
    int e = blockIdx.x * blockDim.x + threadIdx.x;
    if (e < EE) {
        int d = ei[EE + e];
        int pos = atomicAdd(&g_cursor[d], 1);
        g_colidx[pos] = ei[e];
    } else if (e < EE + NN) {
        int i = e - EE;
        int pos = atomicAdd(&g_cursor[i], 1);
        g_colidx[pos] = i;    // self loop
    }
}

// ---------------- fused GEMM + attention-coefficient reduction ----------------
// h = X @ W  (no bias; bias is added post-aggregation, matching reference)
// alpha_src[n,h] = sum_c h[n,h,c]*a_s[h,c]; alpha_dst likewise.
// Block: FOUT threads (one per output col), R=8 rows per block; W reused 8x per load.
template <int FIN, int FOUT, int HEADS_T, bool USE_GH>
__global__ void k_gemm(const float* __restrict__ Xin, const float* __restrict__ W,
                       const float* __restrict__ a_s, const float* __restrict__ a_d) {
    const int R = 8;
    __shared__ float xs[R * FIN];
    const float* __restrict__ X = USE_GH ? (const float*)g_h : Xin;

    int j = threadIdx.x;              // output column
    int base = blockIdx.x * R;

    for (int i = j; i < R * FIN; i += FOUT) {
        int r = i / FIN, k = i - r * FIN;
        int row = base + r;
        xs[i] = (row < NN) ? X[row * FIN + k] : 0.f;
    }
    __syncthreads();

    float acc[R];
    #pragma unroll
    for (int r = 0; r < R; r++) acc[r] = 0.f;

    const float4* xs4 = reinterpret_cast<const float4*>(xs);
    #pragma unroll 2
    for (int k4 = 0; k4 < FIN / 4; k4++) {
        float w0 = W[(4 * k4 + 0) * FOUT + j];
        float w1 = W[(4 * k4 + 1) * FOUT + j];
        float w2 = W[(4 * k4 + 2) * FOUT + j];
        float w3 = W[(4 * k4 + 3) * FOUT + j];
        #pragma unroll
        for (int r = 0; r < R; r++) {
            float4 xv = xs4[r * (FIN / 4) + k4];
            acc[r] += xv.x * w0 + xv.y * w1 + xv.z * w2 + xv.w * w3;
        }
    }

    float asf = a_s[j], adf = a_d[j];
    int lane = j & 31;
    int head = j >> 5;                 // C=32 -> warp == head
    #pragma unroll
    for (int r = 0; r < R; r++) {
        int row = base + r;
        if (row < NN) g_hw[row * FOUT + j] = acc[r];
        float vs = acc[r] * asf, vd = acc[r] * adf;
        #pragma unroll
        for (int off = 16; off; off >>= 1) {
            vs += __shfl_xor_sync(0xffffffffu, vs, off);
            vd += __shfl_xor_sync(0xffffffffu, vd, off);
        }
        if (lane == 0 && row < NN) {
            g_asrc[row * HEADS_T + head] = vs;
            g_adst[row * HEADS_T + head] = vd;
        }
    }
}

// ---------------- per-(dst,head) warp online-softmax aggregation ----------------
template <int HEADS_T, int C_T, bool LAST>
__global__ void k_agg(const float* __restrict__ bias, float* __restrict__ OUT) {
    int gw = (blockIdx.x * blockDim.x + threadIdx.x) >> 5;
    int lane = threadIdx.x & 31;
    if (gw >= NN * HEADS_T) return;
    int dst = gw / HEADS_T;
    int head = gw - dst * HEADS_T;

    float adv = g_adst[dst * HEADS_T + head];
    int p0 = g_rowptr[dst], p1 = g_rowptr[dst + 1];

    float m = -1e30f, s = 0.f, acc = 0.f;
    for (int p = p0; p < p1; p++) {
        int src = g_colidx[p];
        float l = g_asrc[src * HEADS_T + head] + adv;
        l = (l >= 0.f) ? l : NEG_SLOPE * l;
        float hv = g_hw[src * (HEADS_T * C_T) + head * C_T + lane];
        if (l > m) {
            float rr = __expf(m - l);
            s *= rr; acc *= rr; m = l;
        }
        float e = __expf(l - m);
        s += e;
        acc += e * hv;
    }
    float o = acc / (s + 1e-16f) + bias[head * C_T + lane];
    if (LAST) {
        OUT[dst * C_T + lane] = o;                 // heads=1, mean == identity
    } else {
        o = (o > 0.f) ? o : expm1f(o);             // ELU for next layer input
        g_h[dst * HEADS_T * C_T + head * C_T + lane] = o;
    }
}

// ---------------- launch ----------------
extern "C" void kernel_launch(void* const* d_in, const int* in_sizes, int n_in,
                              void* d_out, int out_size) {
    const float* x   = (const float*)d_in[0];
    const int*   ei  = (const int*)  d_in[1];
    const float* W1  = (const float*)d_in[2];
    const float* as1 = (const float*)d_in[3];
    const float* ad1 = (const float*)d_in[4];
    const float* b1  = (const float*)d_in[5];
    const float* W2  = (const float*)d_in[6];
    const float* as2 = (const float*)d_in[7];
    const float* ad2 = (const float*)d_in[8];
    const float* b2  = (const float*)d_in[9];
    const float* W3  = (const float*)d_in[10];
    const float* as3 = (const float*)d_in[11];
    const float* ad3 = (const float*)d_in[12];
    const float* b3  = (const float*)d_in[13];
    float* out = (float*)d_out;

    // CSR by destination (self-loops included)
    k_init_count<<<(NN + 255) / 256, 256>>>();
    k_count<<<(EE + 255) / 256, 256>>>(ei);
    k_scan<<<1, 1024>>>();
    k_fill<<<(ETOT + 255) / 256, 256>>>(ei);

    const int gemm_blocks = (NN + 7) / 8;
    const int agg_blocks_h4 = (NN * HH * 32 + 255) / 256;
    const int agg_blocks_h1 = (NN * 1 * 32 + 255) / 256;

    // layer 1: x[N,128] -> hw[N,128]; aggregate -> g_h (ELU(out+b1))
    k_gemm<DIM, DIM, HH, false><<<gemm_blocks, DIM>>>(x, W1, as1, ad1);
    k_agg<HH, CC, false><<<agg_blocks_h4, 256>>>(b1, out);

    // layer 2: g_h -> hw; aggregate -> g_h
    k_gemm<DIM, DIM, HH, true><<<gemm_blocks, DIM>>>(nullptr, W2, as2, ad2);
    k_agg<HH, CC, false><<<agg_blocks_h4, 256>>>(b2, out);

    // layer 3: g_h -> hw[N,32]; aggregate -> out (+b3), single head
    k_gemm<DIM, CC, 1, true><<<gemm_blocks, CC>>>(nullptr, W3, as3, ad3);
    k_agg<1, CC, true><<<agg_blocks_h1, 256>>>(b3, out);
}

// round 3
// speedup vs baseline: 1.5586x; 1.5586x over previous
#include <cuda_runtime.h>
#include <math.h>

#define NN 50000
#define EE 800000
#define ETOT (EE + NN)
#define DIM 128
#define HH 4
#define CC 32
#define NEG_SLOPE 0.2f

// ---------------- device scratch (no allocations allowed) ----------------
__device__ int    g_count[NN];
__device__ int    g_rowptr[NN + 1];
__device__ int    g_cursor[NN];
__device__ int    g_colidx[ETOT];
__device__ float  g_h[NN * DIM];      // activated layer input (layers 2,3)
__device__ float  g_hw[NN * DIM];     // transformed features of current layer
__device__ float  g_asrc[NN * HH];
__device__ float  g_adst[NN * HH];
__device__ float2 g_Wp[(DIM / 2) * DIM];   // K-pair packed weights (reused per layer)

// ---------------- CSR build ----------------
__global__ void k_init_count() {
    int i = blockIdx.x * blockDim.x + threadIdx.x;
    if (i < NN) g_count[i] = 1;   // self loop pre-counted
}

__global__ void k_count(const int* __restrict__ ei) {
    int e = blockIdx.x * blockDim.x + threadIdx.x;
    if (e < EE) atomicAdd(&g_count[ei[EE + e]], 1);
}

// single-block shuffle-based exclusive scan (N=50000)
__global__ void k_scan() {
    __shared__ int wsum[32];
    __shared__ int carry_s;
    int lane = threadIdx.x & 31;
    int wid  = threadIdx.x >> 5;
    if (threadIdx.x == 0) carry_s = 0;
    __syncthreads();
    for (int base = 0; base < NN; base += 1024) {
        int i = base + threadIdx.x;
        int v = (i < NN) ? g_count[i] : 0;
        // warp inclusive scan
        int x = v;
        #pragma unroll
        for (int off = 1; off < 32; off <<= 1) {
            int t = __shfl_up_sync(0xffffffffu, x, off);
            if (lane >= off) x += t;
        }
        if (lane == 31) wsum[wid] = x;
        __syncthreads();
        if (wid == 0) {
            int y = wsum[lane];
            #pragma unroll
            for (int off = 1; off < 32; off <<= 1) {
                int t = __shfl_up_sync(0xffffffffu, y, off);
                if (lane >= off) y += t;
            }
            wsum[lane] = y;   // inclusive warp-prefix totals
        }
        __syncthreads();
        int wpre = (wid > 0) ? wsum[wid - 1] : 0;
        int excl = carry_s + wpre + x - v;
        if (i < NN) { g_rowptr[i] = excl; g_cursor[i] = excl; }
        int tot = wsum[31];
        __syncthreads();
        if (threadIdx.x == 0) carry_s += tot;
        __syncthreads();
    }
    if (threadIdx.x == 0) g_rowptr[NN] = carry_s;   // == ETOT
}

__global__ void k_fill(const int* __restrict__ ei) {
    int e = blockIdx.x * blockDim.x + threadIdx.x;
    if (e < EE) {
        int d = ei[EE + e];
        int pos = atomicAdd(&g_cursor[d], 1);
        g_colidx[pos] = ei[e];
    } else if (e < EE + NN) {
        int i = e - EE;
        int pos = atomicAdd(&g_cursor[i], 1);
        g_colidx[pos] = i;    // self loop
    }
}

// ---------------- weight K-pair packing ----------------
// g_Wp[k2*FOUT + j] = (W[2*k2][j], W[2*k2+1][j])
__global__ void k_packW(const float* __restrict__ W, int FIN, int FOUT) {
    int i = blockIdx.x * blockDim.x + threadIdx.x;
    int n = (FIN / 2) * FOUT;
    if (i < n) {
        int k2 = i / FOUT, j = i - k2 * FOUT;
        g_Wp[i] = make_float2(W[(2 * k2) * FOUT + j], W[(2 * k2 + 1) * FOUT + j]);
    }
}

__device__ __forceinline__ void ffma2(unsigned long long& d,
                                      unsigned long long a, unsigned long long b) {
    asm("fma.rn.f32x2 %0, %1, %2, %0;" : "+l"(d) : "l"(a), "l"(b));
}

// ---------------- GEMM + attention-coefficient reduction ----------------
// Warp handles 8 rows x FOUT cols. Lane owns NC=FOUT/32 columns (one per head).
// K packed in pairs -> FFMA2. acc halves = even/odd-K partial sums.
template <int FIN, int FOUT, int HEADS_T, bool USE_GH>
__global__ void k_gemm(const float* __restrict__ Xin,
                       const float* __restrict__ a_s, const float* __restrict__ a_d) {
    const int R = 8;
    const int NC = FOUT / 32;
    __shared__ float4 xs[4][R][FIN / 4];
    int lane = threadIdx.x & 31, wip = threadIdx.x >> 5;
    int base = (blockIdx.x * 4 + wip) * R;
    const float* __restrict__ X = USE_GH ? (const float*)g_h : Xin;

    #pragma unroll
    for (int r = 0; r < R; r++) {
        int row = base + r;
        float4 v = make_float4(0.f, 0.f, 0.f, 0.f);
        if (row < NN) v = reinterpret_cast<const float4*>(X + (size_t)row * FIN)[lane];
        xs[wip][r][lane] = v;
    }
    __syncwarp();

    unsigned long long acc[R][NC];
    #pragma unroll
    for (int r = 0; r < R; r++)
        #pragma unroll
        for (int c = 0; c < NC; c++) acc[r][c] = 0ull;

    const float2* __restrict__ Wp = g_Wp;
    #pragma unroll 4
    for (int k4 = 0; k4 < FIN / 4; k4++) {
        unsigned long long wA[NC], wB[NC];
        #pragma unroll
        for (int c = 0; c < NC; c++) {
            wA[c] = *reinterpret_cast<const unsigned long long*>(
                        &Wp[(2 * k4) * FOUT + c * 32 + lane]);
            wB[c] = *reinterpret_cast<const unsigned long long*>(
                        &Wp[(2 * k4 + 1) * FOUT + c * 32 + lane]);
        }
        #pragma unroll
        for (int r = 0; r < R; r++) {
            ulonglong2 xv = reinterpret_cast<const ulonglong2*>(&xs[wip][r][0])[k4];
            #pragma unroll
            for (int c = 0; c < NC; c++) {
                ffma2(acc[r][c], wA[c], xv.x);
                ffma2(acc[r][c], wB[c], xv.y);
            }
        }
    }

    float asv[NC], adv[NC];
    #pragma unroll
    for (int c = 0; c < NC; c++) {
        asv[c] = a_s[c * 32 + lane];
        adv[c] = a_d[c * 32 + lane];
    }

    #pragma unroll
    for (int r = 0; r < R; r++) {
        int row = base + r;
        #pragma unroll
        for (int c = 0; c < NC; c++) {
            unsigned long long a = acc[r][c];
            float h = __uint_as_float((unsigned)(a & 0xffffffffull)) +
                      __uint_as_float((unsigned)(a >> 32));
            if (row < NN) g_hw[(size_t)row * FOUT + c * 32 + lane] = h;
            float vs = h * asv[c], vd = h * adv[c];
            #pragma unroll
            for (int off = 16; off; off >>= 1) {
                vs += __shfl_xor_sync(0xffffffffu, vs, off);
                vd += __shfl_xor_sync(0xffffffffu, vd, off);
            }
            if (lane == 0 && row < NN) {
                g_asrc[row * HEADS_T + c] = vs;
                g_adst[row * HEADS_T + c] = vd;
            }
        }
    }
}

// ---------------- per-(dst,head) warp vectorized online-softmax aggregation ----
template <int HEADS_T, bool LAST>
__global__ void k_agg(const float* __restrict__ bias, float* __restrict__ OUT) {
    __shared__ float2 stage[8][32];   // (weight, src bits)
    int wip = threadIdx.x >> 5, lane = threadIdx.x & 31;
    int gw = blockIdx.x * 8 + wip;
    if (gw >= NN * HEADS_T) return;
    int dst, head;
    if (HEADS_T == 4) { dst = gw >> 2; head = gw & 3; }
    else             { dst = gw;      head = 0; }
    const int FW = HEADS_T * CC;
    const float* __restrict__ hwbase = g_hw + head * CC + lane;

    float adv = g_adst[dst * HEADS_T + head];
    int p0 = g_rowptr[dst], p1 = g_rowptr[dst + 1];

    float m = -1e30f, s = 0.f, acc0 = 0.f, acc1 = 0.f;
    for (int b = p0; b < p1; b += 32) {
        int p = b + lane;
        int src = 0;
        float l = -1e30f;
        if (p < p1) {
            src = g_colidx[p];
            float t = g_asrc[src * HEADS_T + head] + adv;
            l = (t >= 0.f) ? t : NEG_SLOPE * t;
        }
        float cm = l;
        #pragma unroll
        for (int off = 16; off; off >>= 1)
            cm = fmaxf(cm, __shfl_xor_sync(0xffffffffu, cm, off));
        float nm = fmaxf(m, cm);
        float sc = __expf(m - nm);
        s *= sc; acc0 *= sc; acc1 *= sc; m = nm;
        float e = (p < p1) ? __expf(l - m) : 0.f;
        float cs = e;
        #pragma unroll
        for (int off = 16; off; off >>= 1)
            cs += __shfl_xor_sync(0xffffffffu, cs, off);
        s += cs;
        stage[wip][lane] = make_float2(e, __int_as_float(src));
        __syncwarp();
        int cnt = min(32, p1 - b);
        int j = 0;
        #pragma unroll 2
        for (; j + 2 <= cnt; j += 2) {
            float2 a0 = stage[wip][j];
            float2 a1 = stage[wip][j + 1];
            acc0 += a0.x * hwbase[__float_as_int(a0.y) * FW];
            acc1 += a1.x * hwbase[__float_as_int(a1.y) * FW];
        }
        if (j < cnt) {
            float2 a0 = stage[wip][j];
            acc0 += a0.x * hwbase[__float_as_int(a0.y) * FW];
        }
        __syncwarp();
    }
    float o = (acc0 + acc1) / (s + 1e-16f) + bias[head * CC + lane];
    if (LAST) {
        OUT[dst * CC + lane] = o;                 // heads=1, mean == identity
    } else {
        o = (o > 0.f) ? o : expm1f(o);            // ELU for next layer input
        g_h[dst * FW + head * CC + lane] = o;
    }
}

// ---------------- launch ----------------
extern "C" void kernel_launch(void* const* d_in, const int* in_sizes, int n_in,
                              void* d_out, int out_size) {
    const float* x   = (const float*)d_in[0];
    const int*   ei  = (const int*)  d_in[1];
    const float* W1  = (const float*)d_in[2];
    const float* as1 = (const float*)d_in[3];
    const float* ad1 = (const float*)d_in[4];
    const float* b1  = (const float*)d_in[5];
    const float* W2  = (const float*)d_in[6];
    const float* as2 = (const float*)d_in[7];
    const float* ad2 = (const float*)d_in[8];
    const float* b2  = (const float*)d_in[9];
    const float* W3  = (const float*)d_in[10];
    const float* as3 = (const float*)d_in[11];
    const float* ad3 = (const float*)d_in[12];
    const float* b3  = (const float*)d_in[13];
    float* out = (float*)d_out;

    // CSR by destination (self-loops included)
    k_init_count<<<(NN + 255) / 256, 256>>>();
    k_count<<<(EE + 255) / 256, 256>>>(ei);
    k_scan<<<1, 1024>>>();
    k_fill<<<(ETOT + 255) / 256, 256>>>(ei);

    const int gemm_blocks = (NN + 31) / 32;
    const int agg_blocks_h4 = (NN * HH + 7) / 8;
    const int agg_blocks_h1 = (NN + 7) / 8;
    const int pack_big = ((DIM / 2) * DIM + 255) / 256;
    const int pack_sm  = ((DIM / 2) * CC + 255) / 256;

    // layer 1
    k_packW<<<pack_big, 256>>>(W1, DIM, DIM);
    k_gemm<DIM, DIM, HH, false><<<gemm_blocks, 128>>>(x, as1, ad1);
    k_agg<HH, false><<<agg_blocks_h4, 256>>>(b1, out);

    // layer 2
    k_packW<<<pack_big, 256>>>(W2, DIM, DIM);
    k_gemm<DIM, DIM, HH, true><<<gemm_blocks, 128>>>(nullptr, as2, ad2);
    k_agg<HH, false><<<agg_blocks_h4, 256>>>(b2, out);

    // layer 3
    k_packW<<<pack_sm, 256>>>(W3, DIM, CC);
    k_gemm<DIM, CC, 1, true><<<gemm_blocks, 128>>>(nullptr, as3, ad3);
    k_agg<1, true><<<agg_blocks_h1, 256>>>(b3, out);
}